// round 3
// baseline (speedup 1.0000x reference)
#include <cuda_runtime.h>
#include <math.h>

#define NBOX 4096
#define NT   256
#define NW   (NT / 32)       // 8 warps
#define EPT  (NBOX / NT)     // 16 elements per thread
#define FULL 0xFFFFFFFFu

// Shared memory: broadcast tables + double-buffered warp-argmax partials.
struct Smem {
    float4             sbox[NBOX];     // 64 KB
    int                slab[NBOX];     // 16 KB
    unsigned long long part[2][NW];    // packed (key<<32)|~idx partials
};

extern __shared__ char smem_raw[];

__global__ __launch_bounds__(NT, 1)
void softnms_kernel(const float* __restrict__ g_boxes,
                    const float* __restrict__ g_scores,
                    const int*   __restrict__ g_labels,
                    float*       __restrict__ g_out)
{
    Smem* sm = reinterpret_cast<Smem*>(smem_raw);
    const int tid = threadIdx.x;
    const int wid = tid >> 5;
    const int lid = tid & 31;

    // Register-resident per-thread state (thread owns j = tid + k*NT).
    float sc[EPT];
    float bx[EPT], by[EPT], bz[EPT], bw[EPT];
    float ar[EPT];
    int   lb[EPT];

#pragma unroll
    for (int k = 0; k < EPT; k++) {
        int j = tid + k * NT;
        float4 b = reinterpret_cast<const float4*>(g_boxes)[j];
        bx[k] = b.x; by[k] = b.y; bz[k] = b.z; bw[k] = b.w;
        ar[k] = (b.z - b.x) * (b.w - b.y);
        sc[k] = g_scores[j];
        lb[k] = g_labels[j];
        sm->sbox[j] = b;
        sm->slab[j] = lb[k];
    }
    __syncthreads();

    float* outBoxes  = g_out;             // [N,4]
    float* outScores = g_out + 4 * NBOX;  // [N]
    float* outLabels = g_out + 5 * NBOX;  // [N] float; -1 padding

    bool changed = true;                  // force initial computation
    unsigned long long localP = 0ULL;     // cached thread partial
    unsigned long long warpP  = 0ULL;     // cached warp partial (all lanes)

    int t;
    for (t = 0; t < NBOX; t++) {
        const int buf = t & 1;

        // ---- lazy local argmax: packed (keybits<<32) | ~idx, tree reduce ----
        if (changed) {
            unsigned long long v[EPT];
#pragma unroll
            for (int k = 0; k < EPT; k++) {
                unsigned kk = __float_as_uint(fmaxf(sc[k], 0.0f)); // -INF -> 0
                v[k] = ((unsigned long long)kk << 32)
                     | (unsigned)~(tid + k * NT);
            }
#pragma unroll
            for (int s = EPT / 2; s > 0; s >>= 1)
#pragma unroll
                for (int k = 0; k < s; k++)
                    v[k] = (v[k + s] > v[k]) ? v[k + s] : v[k];
            localP = v[0];
        }

        // ---- lazy warp argmax (only if any lane changed) ----
        unsigned cm = __ballot_sync(FULL, changed);
        if (cm) {
            unsigned khi  = (unsigned)(localP >> 32);
            unsigned wmax = __reduce_max_sync(FULL, khi);
            unsigned lo   = (khi == wmax) ? (unsigned)localP : 0u;
            unsigned wlo  = __reduce_max_sync(FULL, lo);   // max ~j == min j
            warpP = ((unsigned long long)wmax << 32) | wlo;
        }
        changed = false;
        if (lid == 0) sm->part[buf][wid] = warpP;
        __syncthreads();                                   // only barrier

        // ---- final reduce over NW partials, redundantly in every warp ----
        unsigned long long p = (lid < NW) ? sm->part[buf][lid] : 0ULL;
        unsigned khi = (unsigned)(p >> 32);
        unsigned M   = __reduce_max_sync(FULL, khi);
        if (M == 0u) break;                                // uniform exit
        unsigned lo  = (khi == M) ? (unsigned)p : 0u;
        unsigned wlo = __reduce_max_sync(FULL, lo);
        int SI = (int)~wlo;                                // winner index

        // Broadcast selected box (same-address LDS).
        float4 sb = sm->sbox[SI];
        int    sl = sm->slab[SI];
        float  a1 = (sb.z - sb.x) * (sb.w - sb.y);

        if (tid == 0) {
            reinterpret_cast<float4*>(outBoxes)[t] = sb;
            outScores[t] = __uint_as_float(M);             // score BEFORE decay
            outLabels[t] = (float)sl;
        }

        // ---- decay owned elements (registers only) ----
#pragma unroll
        for (int k = 0; k < EPT; k++) {
            int j = tid + k * NT;
            float v = sc[k];
            if (v != -INFINITY) {
                if (j == SI) {
                    sc[k] = -INFINITY; changed = true;     // deactivate selected
                } else if (lb[k] == sl) {
                    float w = fminf(sb.z, bz[k]) - fmaxf(sb.x, bx[k]);
                    float h = fminf(sb.w, bw[k]) - fmaxf(sb.y, by[k]);
                    if (w > 0.0f && h > 0.0f) {
                        float inter = w * h;
                        float iou = inter / ((a1 + ar[k]) - inter + 1e-8f);
                        float d   = expf(-(iou * iou) * 2.0f); // sigma=0.5
                        float nv  = v * d;
                        sc[k] = (nv >= 0.001f) ? nv : -INFINITY;
                        changed = true;
                    }
                }
            }
        }
    }

    // ---- fill remaining (invalid) slots ----
    for (int r = t + tid; r < NBOX; r += NT) {
        reinterpret_cast<float4*>(outBoxes)[r] = make_float4(0.f, 0.f, 0.f, 0.f);
        outScores[r] = 0.0f;
        outLabels[r] = -1.0f;
    }
}

extern "C" void kernel_launch(void* const* d_in, const int* in_sizes, int n_in,
                              void* d_out, int out_size)
{
    const float* boxes  = (const float*)d_in[0];
    const float* scores = (const float*)d_in[1];
    const int*   labels = (const int*)d_in[2];
    float*       out    = (float*)d_out;

    size_t smem = sizeof(Smem);
    cudaFuncSetAttribute(softnms_kernel,
                         cudaFuncAttributeMaxDynamicSharedMemorySize, (int)smem);
    softnms_kernel<<<1, NT, smem>>>(boxes, scores, labels, out);
}

// round 4
// speedup vs baseline: 3.8045x; 3.8045x over previous
#include <cuda_runtime.h>
#include <math.h>

#define NBOX 4096
#define NT   768
#define GSZ  384                  // threads per class-group (12 warps)
#define GW   (GSZ / 32)           // 12 warps per group
#define EPT  6                    // register slots/thread: 6*384=2304 per group
#define FULL 0xFFFFFFFFu

typedef unsigned long long u64;
typedef unsigned u32;

struct Smem {
    float4 sbox[NBOX];            // orig-indexed boxes (broadcast + merge)   64 KB
    float  cscore[NBOX];          // compacted scores (setup + overflow path) 16 KB
    int    corig[NBOX];           // compacted -> orig index                  16 KB
    u64    emit[NBOX];            // emission keys; g0 at [0..), g1 at [n0..) 32 KB
    u64    part[2][2][GW];        // [group][buf][warp] argmax partials
    int    n0;                    // #class-0 boxes
    int    cnt[2];                // compaction cursors
    int    mcnt[2];               // emitted counts per group
};

extern __shared__ char smem_raw[];

__global__ __launch_bounds__(NT, 1)
void softnms_kernel(const float* __restrict__ g_boxes,
                    const float* __restrict__ g_scores,
                    const int*   __restrict__ g_labels,
                    float*       __restrict__ g_out)
{
    Smem* sm = reinterpret_cast<Smem*>(smem_raw);
    const int tid = threadIdx.x;
    const int lid = tid & 31;

    // ================= setup: tables + class compaction =================
    if (tid == 0) sm->n0 = 0;
    __syncthreads();
    {
        int c0 = 0;
        for (int j = tid; j < NBOX; j += NT) {
            sm->sbox[j] = reinterpret_cast<const float4*>(g_boxes)[j];
            if (g_labels[j] == 0) c0++;
        }
        atomicAdd(&sm->n0, c0);
    }
    __syncthreads();
    if (tid == 0) { sm->cnt[0] = 0; sm->cnt[1] = sm->n0; }
    __syncthreads();
    for (int j = tid; j < NBOX; j += NT) {
        int l = g_labels[j];
        int pos = atomicAdd(&sm->cnt[l], 1);
        sm->cscore[pos] = g_scores[j];
        sm->corig[pos]  = j;
    }
    __syncthreads();

    // ================= per-class group scan =================
    const int g    = tid / GSZ;           // class == group
    const int gt   = tid % GSZ;
    const int gw   = gt >> 5;
    const int N0   = sm->n0;
    const int base = g ? N0 : 0;
    const int Ng   = g ? (NBOX - N0) : N0;
    const int lim  = base + Ng;
    const int rbeg = base + EPT * GSZ;    // overflow region start (rare)

    // register-resident owned boxes: compacted index ci = base + gt + k*GSZ
    float sc[EPT], bx[EPT], by[EPT], bz[EPT], bw[EPT], ar[EPT];
    int   org[EPT];
#pragma unroll
    for (int k = 0; k < EPT; k++) {
        int ci = base + gt + k * GSZ;
        if (ci < lim) {
            int o = sm->corig[ci];
            float4 b = sm->sbox[o];
            bx[k] = b.x; by[k] = b.y; bz[k] = b.z; bw[k] = b.w;
            ar[k] = (b.z - b.x) * (b.w - b.y);
            sc[k] = sm->cscore[ci];
            org[k] = o;
        } else { sc[k] = -INFINITY; org[k] = -1; }
    }

    bool changed = true;
    u64 localP = 0ULL, warpP = 0ULL;
    int m = 0;                            // emissions so far (uniform in group)

    for (int t = 0; t < Ng; t++) {
        const int buf = t & 1;

        // ---- lazy local argmax: key = (scorebits<<32) | ~origIdx ----
        if (changed) {
            u64 best = 0ULL;
#pragma unroll
            for (int k = 0; k < EPT; k++) {
                u32 kk = __float_as_uint(fmaxf(sc[k], 0.0f));   // -INF -> 0
                u64 v = ((u64)kk << 32) | (u32)~org[k];
                if (v > best) best = v;
            }
            for (int ci = rbeg + gt; ci < lim; ci += GSZ) {     // overflow (rare)
                u32 kk = __float_as_uint(fmaxf(sm->cscore[ci], 0.0f));
                u64 v = ((u64)kk << 32) | (u32)~sm->corig[ci];
                if (v > best) best = v;
            }
            localP = best;
        }

        // ---- lazy warp argmax ----
        if (__ballot_sync(FULL, changed)) {
            u32 hi = (u32)(localP >> 32);
            u32 wm = __reduce_max_sync(FULL, hi);
            u32 lo = (hi == wm) ? (u32)localP : 0u;
            u32 wl = __reduce_max_sync(FULL, lo);
            warpP = ((u64)wm << 32) | wl;
        }
        changed = false;
        if (lid == 0) sm->part[g][buf][gw] = warpP;
        asm volatile("bar.sync %0, %1;" :: "r"(g + 1), "r"(GSZ) : "memory");

        // ---- final reduce over GW partials, redundantly in each warp ----
        u64 p = (lid < GW) ? sm->part[g][buf][lid] : 0ULL;
        u32 hi = (u32)(p >> 32);
        u32 M  = __reduce_max_sync(FULL, hi);
        if (M == 0u) break;                                     // group done
        u32 lo  = (hi == M) ? (u32)p : 0u;
        u32 wl  = __reduce_max_sync(FULL, lo);
        int sorig = (int)~wl;

        float4 sb = sm->sbox[sorig];                            // broadcast LDS
        float  a1 = (sb.z - sb.x) * (sb.w - sb.y);
        if (gt == 0) sm->emit[base + m] = ((u64)M << 32) | wl;
        m++;

        // ---- decay owned boxes (all same class by construction) ----
#pragma unroll
        for (int k = 0; k < EPT; k++) {
            float v = sc[k];
            if (v != -INFINITY) {
                if (org[k] == sorig) { sc[k] = -INFINITY; changed = true; }
                else {
                    float w = fminf(sb.z, bz[k]) - fmaxf(sb.x, bx[k]);
                    float h = fminf(sb.w, bw[k]) - fmaxf(sb.y, by[k]);
                    if (w > 0.0f && h > 0.0f) {
                        float inter = w * h;
                        float iou = inter / ((a1 + ar[k]) - inter + 1e-8f);
                        float d   = expf(-(iou * iou) * 2.0f);  // sigma=0.5
                        float nv  = v * d;
                        sc[k] = (nv >= 0.001f) ? nv : -INFINITY;
                        changed = true;
                    }
                }
            }
        }
        // overflow region (rare; smem-resident)
        for (int ci = rbeg + gt; ci < lim; ci += GSZ) {
            float v = sm->cscore[ci];
            if (v != -INFINITY) {
                int o = sm->corig[ci];
                if (o == sorig) { sm->cscore[ci] = -INFINITY; changed = true; }
                else {
                    float4 b = sm->sbox[o];
                    float w = fminf(sb.z, b.z) - fmaxf(sb.x, b.x);
                    float h = fminf(sb.w, b.w) - fmaxf(sb.y, b.y);
                    if (w > 0.0f && h > 0.0f) {
                        float a2 = (b.z - b.x) * (b.w - b.y);
                        float inter = w * h;
                        float iou = inter / ((a1 + a2) - inter + 1e-8f);
                        float d   = expf(-(iou * iou) * 2.0f);
                        float nv  = v * d;
                        sm->cscore[ci] = (nv >= 0.001f) ? nv : -INFINITY;
                        changed = true;
                    }
                }
            }
        }
    }

    if (gt == 0) sm->mcnt[g] = m;
    __syncthreads();

    // ================= merge the two sorted emission lists =================
    float* outBoxes  = g_out;             // [N,4]
    float* outScores = g_out + 4 * NBOX;  // [N]
    float* outLabels = g_out + 5 * NBOX;  // [N] float; -1 padding

    const int mA = sm->mcnt[0];
    const int mB = sm->mcnt[1];
    const u64* eA = sm->emit;             // descending keys, class 0
    const u64* eB = sm->emit + N0;        // descending keys, class 1

    for (int i = tid; i < mA; i += NT) {
        u64 key = eA[i];
        int lo = 0, hi = mB;
        while (lo < hi) { int mid = (lo + hi) >> 1;
                          if (eB[mid] > key) lo = mid + 1; else hi = mid; }
        int r = i + lo;
        int o = (int)~(u32)key;
        reinterpret_cast<float4*>(outBoxes)[r] = sm->sbox[o];
        outScores[r] = __uint_as_float((u32)(key >> 32));
        outLabels[r] = 0.0f;
    }
    for (int i = tid; i < mB; i += NT) {
        u64 key = eB[i];
        int lo = 0, hi = mA;
        while (lo < hi) { int mid = (lo + hi) >> 1;
                          if (eA[mid] > key) lo = mid + 1; else hi = mid; }
        int r = i + lo;
        int o = (int)~(u32)key;
        reinterpret_cast<float4*>(outBoxes)[r] = sm->sbox[o];
        outScores[r] = __uint_as_float((u32)(key >> 32));
        outLabels[r] = 1.0f;
    }
    for (int r = mA + mB + tid; r < NBOX; r += NT) {
        reinterpret_cast<float4*>(outBoxes)[r] = make_float4(0.f, 0.f, 0.f, 0.f);
        outScores[r] = 0.0f;
        outLabels[r] = -1.0f;
    }
}

extern "C" void kernel_launch(void* const* d_in, const int* in_sizes, int n_in,
                              void* d_out, int out_size)
{
    const float* boxes  = (const float*)d_in[0];
    const float* scores = (const float*)d_in[1];
    const int*   labels = (const int*)d_in[2];
    float*       out    = (float*)d_out;

    size_t smem = sizeof(Smem);
    cudaFuncSetAttribute(softnms_kernel,
                         cudaFuncAttributeMaxDynamicSharedMemorySize, (int)smem);
    softnms_kernel<<<1, NT, smem>>>(boxes, scores, labels, out);
}

// round 5
// speedup vs baseline: 4.0272x; 1.0585x over previous
#include <cuda_runtime.h>
#include <math.h>

#define NBOX 4096
#define NT   256                 // threads per class CTA (8 warps)
#define NW   (NT / 32)
#define EPT  9                   // 9*256 = 2304 register capacity per class
#define FULL 0xFFFFFFFFu

typedef unsigned long long u64;
typedef unsigned u32;

// Global scratch (static device arrays — no allocation).
__device__ u64 g_emit[2][NBOX];  // per-class emission keys, descending
__device__ int g_mcnt[2];

// ---------------- per-class scan kernel (grid = 2, one CTA per class) ----
struct ScanSmem {
    float4 sbox[NBOX];           // orig-indexed boxes (broadcast lookup) 64 KB
    float  cscore[NBOX];         // compacted scores                      16 KB
    int    corig[NBOX];          // compacted -> orig index               16 KB
    u64    part[2][NW];          // double-buffered warp argmax partials
    int    cnt;                  // compaction cursor
};

extern __shared__ char smem_raw[];

__global__ __launch_bounds__(NT, 1)
void scan_kernel(const float* __restrict__ g_boxes,
                 const float* __restrict__ g_scores,
                 const int*   __restrict__ g_labels)
{
    ScanSmem* sm = reinterpret_cast<ScanSmem*>(smem_raw);
    const int cls = blockIdx.x;          // class handled by this CTA
    const int tid = threadIdx.x;
    const int wid = tid >> 5;
    const int lid = tid & 31;

    // ---- load boxes + compact own class ----
    if (tid == 0) sm->cnt = 0;
    __syncthreads();
    for (int j = tid; j < NBOX; j += NT) {
        float4 b = reinterpret_cast<const float4*>(g_boxes)[j];
        sm->sbox[j] = b;
        if (g_labels[j] == cls) {
            int pos = atomicAdd(&sm->cnt, 1);
            sm->cscore[pos] = g_scores[j];
            sm->corig[pos]  = j;
        }
    }
    __syncthreads();
    const int Ng   = sm->cnt;
    const int rbeg = EPT * NT;           // smem overflow start (rare)

    // ---- register-resident owned slots: ci = tid + k*NT ----
    float sc[EPT], bx[EPT], by[EPT], bz[EPT], bw[EPT], ar[EPT];
    int   org[EPT];
#pragma unroll
    for (int k = 0; k < EPT; k++) {
        int ci = tid + k * NT;
        if (ci < Ng) {
            int o = sm->corig[ci];
            float4 b = sm->sbox[o];
            bx[k] = b.x; by[k] = b.y; bz[k] = b.z; bw[k] = b.w;
            ar[k] = (b.z - b.x) * (b.w - b.y);
            sc[k] = sm->cscore[ci];
            org[k] = o;
        } else { sc[k] = -INFINITY; org[k] = -1; }
    }

    bool changed = true;
    u64  localP = 0ULL, warpP = 0ULL;
    int  m = 0;

    for (int t = 0; t < Ng; t++) {
        const int buf = t & 1;

        // lazy local argmax: key = (scorebits<<32) | ~origIdx
        if (changed) {
            u64 best = 0ULL;
#pragma unroll
            for (int k = 0; k < EPT; k++) {
                u32 kk = __float_as_uint(fmaxf(sc[k], 0.0f));   // -INF -> 0
                u64 v = ((u64)kk << 32) | (u32)~org[k];
                if (v > best) best = v;
            }
            for (int ci = rbeg + tid; ci < Ng; ci += NT) {      // overflow
                u32 kk = __float_as_uint(fmaxf(sm->cscore[ci], 0.0f));
                u64 v = ((u64)kk << 32) | (u32)~sm->corig[ci];
                if (v > best) best = v;
            }
            localP = best;
        }

        // lazy warp argmax
        if (__ballot_sync(FULL, changed)) {
            u32 hi = (u32)(localP >> 32);
            u32 wm = __reduce_max_sync(FULL, hi);
            u32 lo = (hi == wm) ? (u32)localP : 0u;
            u32 wl = __reduce_max_sync(FULL, lo);               // max ~j == min j
            warpP = ((u64)wm << 32) | wl;
        }
        changed = false;
        if (lid == 0) sm->part[buf][wid] = warpP;
        __syncthreads();

        // final reduce over NW partials, redundantly in every warp
        u64 p = (lid < NW) ? sm->part[buf][lid] : 0ULL;
        u32 hi = (u32)(p >> 32);
        u32 M  = __reduce_max_sync(FULL, hi);
        if (M == 0u) break;
        u32 lo = (hi == M) ? (u32)p : 0u;
        u32 wl = __reduce_max_sync(FULL, lo);
        int sorig = (int)~wl;

        float4 sb = sm->sbox[sorig];                            // broadcast LDS
        float  a1 = (sb.z - sb.x) * (sb.w - sb.y);
        if (tid == 0) g_emit[cls][m] = ((u64)M << 32) | wl;
        m++;

        // decay owned boxes (all same class by construction)
#pragma unroll
        for (int k = 0; k < EPT; k++) {
            float v = sc[k];
            if (v != -INFINITY) {
                if (org[k] == sorig) { sc[k] = -INFINITY; changed = true; }
                else {
                    float w = fminf(sb.z, bz[k]) - fmaxf(sb.x, bx[k]);
                    float h = fminf(sb.w, bw[k]) - fmaxf(sb.y, by[k]);
                    if (w > 0.0f && h > 0.0f) {
                        float inter = w * h;
                        float iou = inter / ((a1 + ar[k]) - inter + 1e-8f);
                        float d   = expf(-(iou * iou) * 2.0f);  // sigma=0.5
                        float nv  = v * d;
                        sc[k] = (nv >= 0.001f) ? nv : -INFINITY;
                        changed = true;
                    }
                }
            }
        }
        for (int ci = rbeg + tid; ci < Ng; ci += NT) {          // overflow (rare)
            float v = sm->cscore[ci];
            if (v != -INFINITY) {
                int o = sm->corig[ci];
                if (o == sorig) { sm->cscore[ci] = -INFINITY; changed = true; }
                else {
                    float4 b = sm->sbox[o];
                    float w = fminf(sb.z, b.z) - fmaxf(sb.x, b.x);
                    float h = fminf(sb.w, b.w) - fmaxf(sb.y, b.y);
                    if (w > 0.0f && h > 0.0f) {
                        float a2 = (b.z - b.x) * (b.w - b.y);
                        float inter = w * h;
                        float iou = inter / ((a1 + a2) - inter + 1e-8f);
                        float d   = expf(-(iou * iou) * 2.0f);
                        float nv  = v * d;
                        sm->cscore[ci] = (nv >= 0.001f) ? nv : -INFINITY;
                        changed = true;
                    }
                }
            }
        }
    }

    if (tid == 0) g_mcnt[cls] = m;
}

// ---------------- merge kernel (1 CTA) ----------------
__global__ __launch_bounds__(NT, 1)
void merge_kernel(const float* __restrict__ g_boxes,
                  float* __restrict__ g_out)
{
    const int tid = threadIdx.x;
    const int mA = g_mcnt[0];
    const int mB = g_mcnt[1];

    float* outBoxes  = g_out;             // [N,4]
    float* outScores = g_out + 4 * NBOX;  // [N]
    float* outLabels = g_out + 5 * NBOX;  // [N] float; -1 padding

    for (int i = tid; i < mA; i += NT) {
        u64 key = g_emit[0][i];
        int lo = 0, hi = mB;
        while (lo < hi) { int mid = (lo + hi) >> 1;
                          if (g_emit[1][mid] > key) lo = mid + 1; else hi = mid; }
        int r = i + lo;
        int o = (int)~(u32)key;
        reinterpret_cast<float4*>(outBoxes)[r] =
            reinterpret_cast<const float4*>(g_boxes)[o];
        outScores[r] = __uint_as_float((u32)(key >> 32));
        outLabels[r] = 0.0f;
    }
    for (int i = tid; i < mB; i += NT) {
        u64 key = g_emit[1][i];
        int lo = 0, hi = mA;
        while (lo < hi) { int mid = (lo + hi) >> 1;
                          if (g_emit[0][mid] > key) lo = mid + 1; else hi = mid; }
        int r = i + lo;
        int o = (int)~(u32)key;
        reinterpret_cast<float4*>(outBoxes)[r] =
            reinterpret_cast<const float4*>(g_boxes)[o];
        outScores[r] = __uint_as_float((u32)(key >> 32));
        outLabels[r] = 1.0f;
    }
    for (int r = mA + mB + tid; r < NBOX; r += NT) {
        reinterpret_cast<float4*>(outBoxes)[r] = make_float4(0.f, 0.f, 0.f, 0.f);
        outScores[r] = 0.0f;
        outLabels[r] = -1.0f;
    }
}

extern "C" void kernel_launch(void* const* d_in, const int* in_sizes, int n_in,
                              void* d_out, int out_size)
{
    const float* boxes  = (const float*)d_in[0];
    const float* scores = (const float*)d_in[1];
    const int*   labels = (const int*)d_in[2];
    float*       out    = (float*)d_out;

    size_t smem = sizeof(ScanSmem);
    cudaFuncSetAttribute(scan_kernel,
                         cudaFuncAttributeMaxDynamicSharedMemorySize, (int)smem);
    scan_kernel<<<2, NT, smem>>>(boxes, scores, labels);
    merge_kernel<<<1, NT>>>(boxes, out);
}

// round 6
// speedup vs baseline: 4.3574x; 1.0820x over previous
#include <cuda_runtime.h>
#include <math.h>

#define NBOX 4096
#define NT   256                 // threads per class CTA (8 warps)
#define NW   (NT / 32)
#define EPT  9                   // 9*256 = 2304 register capacity per class
#define NCAND (NW * 4)           // 32 candidates: per-warp top-4
#define MAXB 32
#define FULL 0xFFFFFFFFu

typedef unsigned long long u64;
typedef unsigned u32;

__device__ u64 g_emit[2][NBOX];  // per-class emission keys, descending
__device__ int g_mcnt[2];

struct ScanSmem {
    float4 sbox[NBOX];           // orig-indexed boxes                  64 KB
    float  cscore[NBOX];         // compacted scores                    16 KB
    int    corig[NBOX];          // compacted -> orig index             16 KB
    u64    cand[NCAND];          // published candidate keys
    u32    cflag[NCAND];         // 1 = lane's second publication
    int    acc[MAXB];            // accepted orig indices (epoch order)
    int    cnt;
};

extern __shared__ char smem_raw[];

__device__ __forceinline__ u64 packkey(float s, int orig) {
    return ((u64)__float_as_uint(fmaxf(s, 0.0f)) << 32) | (u32)~orig;
}

__global__ __launch_bounds__(NT, 1)
void scan_kernel(const float* __restrict__ g_boxes,
                 const float* __restrict__ g_scores,
                 const int*   __restrict__ g_labels)
{
    ScanSmem* sm = reinterpret_cast<ScanSmem*>(smem_raw);
    const int cls = blockIdx.x;
    const int tid = threadIdx.x;
    const int wid = tid >> 5;
    const int lid = tid & 31;

    // ---- load boxes + compact own class ----
    if (tid == 0) sm->cnt = 0;
    __syncthreads();
    for (int j = tid; j < NBOX; j += NT) {
        float4 b = reinterpret_cast<const float4*>(g_boxes)[j];
        sm->sbox[j] = b;
        if (g_labels[j] == cls) {
            int pos = atomicAdd(&sm->cnt, 1);
            sm->cscore[pos] = g_scores[j];
            sm->corig[pos]  = j;
        }
    }
    __syncthreads();
    const int Ng   = sm->cnt;
    const int rbeg = EPT * NT;   // smem overflow start (rarely populated)

    // ---- register-resident owned slots: ci = tid + k*NT ----
    float sc[EPT], bx[EPT], by[EPT], bz[EPT], bw[EPT], ar[EPT];
    int   org[EPT];
#pragma unroll
    for (int k = 0; k < EPT; k++) {
        int ci = tid + k * NT;
        if (ci < Ng) {
            int o = sm->corig[ci];
            float4 b = sm->sbox[o];
            bx[k] = b.x; by[k] = b.y; bz[k] = b.z; bw[k] = b.w;
            ar[k] = (b.z - b.x) * (b.w - b.y);
            sc[k] = sm->cscore[ci];
            org[k] = o;
        } else { sc[k] = -INFINITY; org[k] = -1; }
    }

    bool changed = true;
    u64  la0 = 0, la1 = 0;       // cached local top-2 (packed keys)
    int  emitted = 0;

    while (true) {
        // ---- recompute local top-2 if owned set changed ----
        if (changed) {
            u64 a = 0, b = 0;
#pragma unroll
            for (int k = 0; k < EPT; k++) {
                u64 v = (sc[k] == -INFINITY) ? 0ULL : packkey(sc[k], org[k]);
                if (v > a) { b = a; a = v; } else if (v > b) b = v;
            }
            for (int ci = rbeg + tid; ci < Ng; ci += NT) {
                float s = sm->cscore[ci];
                u64 v = (s == -INFINITY) ? 0ULL : packkey(s, sm->corig[ci]);
                if (v > a) { b = a; a = v; } else if (v > b) b = v;
            }
            la0 = a; la1 = b;
            changed = false;
        }

        // ---- extract + publish per-warp top-4 candidates ----
        {
            int p = 0;
#pragma unroll
            for (int r = 0; r < 4; r++) {
                u64 contrib = (p == 0) ? la0 : ((p == 1) ? la1 : 0ULL);
                u32 hi = (u32)(contrib >> 32);
                u32 wm = __reduce_max_sync(FULL, hi);
                u32 lo = (hi == wm) ? (u32)contrib : 0u;
                u32 wl = __reduce_max_sync(FULL, lo);
                u64 win = ((u64)wm << 32) | wl;
                if (win != 0ULL && contrib == win) {   // unique winner lane
                    sm->cand[wid * 4 + r]  = win;
                    sm->cflag[wid * 4 + r] = (p == 1) ? 1u : 0u;
                    p++;
                }
                if (win == 0ULL && lid == 0) sm->cand[wid * 4 + r] = 0ULL;
            }
        }
        __syncthreads();

        // ---- load candidates (one per lane) + compute outside bound ----
        u64 ck = sm->cand[lid];
        u32 second = sm->cflag[lid];
        u64 bref = (ck != 0ULL && (second || (lid & 3) == 3)) ? ck : 0ULL;
        u32 bh = (u32)(bref >> 32);
        u32 bm = __reduce_max_sync(FULL, bh);
        u32 bl = (bh == bm) ? (u32)bref : 0u;
        u32 bml = __reduce_max_sync(FULL, bl);
        u64 bound = ((u64)bm << 32) | bml;

        int corig = -1; float csc = 0.0f, ca = 0.0f;
        float4 cb = make_float4(0.f, 0.f, 0.f, 0.f);
        if (ck != 0ULL) {
            corig = (int)~(u32)ck;
            csc = __uint_as_float((u32)(ck >> 32));
            cb = sm->sbox[corig];
            ca = (cb.z - cb.x) * (cb.w - cb.y);
        }
        u64 cur = ck;

        // ---- batch accept loop (redundant in every warp, no barriers) ----
        int bcount = 0;
        while (true) {
            u32 hi = (u32)(cur >> 32);
            u32 wm = __reduce_max_sync(FULL, hi);
            if (wm == 0u) break;                        // candidates exhausted
            u32 lo = (hi == wm) ? (u32)cur : 0u;
            u32 wl = __reduce_max_sync(FULL, lo);
            u64 win = ((u64)wm << 32) | wl;
            if (bcount > 0 && win < bound) break;       // exactness boundary
            int so = (int)~wl;
            if (tid == 0) { g_emit[cls][emitted] = win; sm->acc[bcount] = so; }
            emitted++; bcount++;

            float4 ab = sm->sbox[so];                   // broadcast LDS
            float  aa = (ab.z - ab.x) * (ab.w - ab.y);

            if (cur != 0ULL) {                          // update my candidate
                if (corig == so) cur = 0ULL;
                else {
                    float w = fminf(ab.z, cb.z) - fmaxf(ab.x, cb.x);
                    float h = fminf(ab.w, cb.w) - fmaxf(ab.y, cb.y);
                    if (w > 0.0f && h > 0.0f) {
                        float inter = w * h;
                        float iou = inter / ((aa + ca) - inter + 1e-8f);
                        float d   = expf(-(iou * iou) * 2.0f);
                        float nv  = csc * d;
                        if (nv >= 0.001f) {
                            csc = nv;
                            cur = ((u64)__float_as_uint(csc) << 32) | (u32)~corig;
                        } else cur = 0ULL;
                    }
                }
            }
            if (bcount >= MAXB) break;
        }

        if (bcount == 0) break;                         // class done
        __syncthreads();                                // acc[] visible

        // ---- deferred owned decay, in emission order (bit-exact) ----
        for (int b = 0; b < bcount; b++) {
            int so = sm->acc[b];
            float4 ab = sm->sbox[so];
            float  aa = (ab.z - ab.x) * (ab.w - ab.y);
#pragma unroll
            for (int k = 0; k < EPT; k++) {
                float v = sc[k];
                if (v != -INFINITY) {
                    if (org[k] == so) { sc[k] = -INFINITY; changed = true; }
                    else {
                        float w = fminf(ab.z, bz[k]) - fmaxf(ab.x, bx[k]);
                        float h = fminf(ab.w, bw[k]) - fmaxf(ab.y, by[k]);
                        if (w > 0.0f && h > 0.0f) {
                            float inter = w * h;
                            float iou = inter / ((aa + ar[k]) - inter + 1e-8f);
                            float d   = expf(-(iou * iou) * 2.0f);
                            float nv  = v * d;
                            sc[k] = (nv >= 0.001f) ? nv : -INFINITY;
                            changed = true;
                        }
                    }
                }
            }
            for (int ci = rbeg + tid; ci < Ng; ci += NT) {   // overflow (rare)
                float v = sm->cscore[ci];
                if (v != -INFINITY) {
                    int o = sm->corig[ci];
                    if (o == so) { sm->cscore[ci] = -INFINITY; changed = true; }
                    else {
                        float4 b2 = sm->sbox[o];
                        float w = fminf(ab.z, b2.z) - fmaxf(ab.x, b2.x);
                        float h = fminf(ab.w, b2.w) - fmaxf(ab.y, b2.y);
                        if (w > 0.0f && h > 0.0f) {
                            float a2 = (b2.z - b2.x) * (b2.w - b2.y);
                            float inter = w * h;
                            float iou = inter / ((aa + a2) - inter + 1e-8f);
                            float d   = expf(-(iou * iou) * 2.0f);
                            float nv  = v * d;
                            sm->cscore[ci] = (nv >= 0.001f) ? nv : -INFINITY;
                            changed = true;
                        }
                    }
                }
            }
        }
    }

    if (tid == 0) g_mcnt[cls] = emitted;
}

// ---------------- merge kernel (1 CTA, smem-staged keys) ----------------
#define MNT 256
__global__ __launch_bounds__(MNT, 1)
void merge_kernel(const float* __restrict__ g_boxes,
                  float* __restrict__ g_out)
{
    __shared__ u64 sA[NBOX];     // both lists staged: A at 0, B at mA
    const int tid = threadIdx.x;
    const int mA = g_mcnt[0];
    const int mB = g_mcnt[1];

    for (int i = tid; i < mA; i += MNT) sA[i]      = g_emit[0][i];
    for (int i = tid; i < mB; i += MNT) sA[mA + i] = g_emit[1][i];
    __syncthreads();

    float* outBoxes  = g_out;
    float* outScores = g_out + 4 * NBOX;
    float* outLabels = g_out + 5 * NBOX;

    for (int i = tid; i < mA; i += MNT) {
        u64 key = sA[i];
        int lo = 0, hi = mB;
        while (lo < hi) { int mid = (lo + hi) >> 1;
                          if (sA[mA + mid] > key) lo = mid + 1; else hi = mid; }
        int r = i + lo;
        int o = (int)~(u32)key;
        reinterpret_cast<float4*>(outBoxes)[r] =
            reinterpret_cast<const float4*>(g_boxes)[o];
        outScores[r] = __uint_as_float((u32)(key >> 32));
        outLabels[r] = 0.0f;
    }
    for (int i = tid; i < mB; i += MNT) {
        u64 key = sA[mA + i];
        int lo = 0, hi = mA;
        while (lo < hi) { int mid = (lo + hi) >> 1;
                          if (sA[mid] > key) lo = mid + 1; else hi = mid; }
        int r = i + lo;
        int o = (int)~(u32)key;
        reinterpret_cast<float4*>(outBoxes)[r] =
            reinterpret_cast<const float4*>(g_boxes)[o];
        outScores[r] = __uint_as_float((u32)(key >> 32));
        outLabels[r] = 1.0f;
    }
    for (int r = mA + mB + tid; r < NBOX; r += MNT) {
        reinterpret_cast<float4*>(outBoxes)[r] = make_float4(0.f, 0.f, 0.f, 0.f);
        outScores[r] = 0.0f;
        outLabels[r] = -1.0f;
    }
}

extern "C" void kernel_launch(void* const* d_in, const int* in_sizes, int n_in,
                              void* d_out, int out_size)
{
    const float* boxes  = (const float*)d_in[0];
    const float* scores = (const float*)d_in[1];
    const int*   labels = (const int*)d_in[2];
    float*       out    = (float*)d_out;

    size_t smem = sizeof(ScanSmem);
    cudaFuncSetAttribute(scan_kernel,
                         cudaFuncAttributeMaxDynamicSharedMemorySize, (int)smem);
    scan_kernel<<<2, NT, smem>>>(boxes, scores, labels);
    merge_kernel<<<1, MNT>>>(boxes, out);
}